// round 4
// baseline (speedup 1.0000x reference)
#include <cuda_runtime.h>
#include <cstdint>

// Problem constants
#define BATCH 8
#define NPTS  32768
#define MPTS  (NPTS / 4)     // 8192
#define CINCH 128

// FPS kernel config: one cluster of CSZ CTAs per batch
#define CSZ   8
#define TPB   512
#define PPC   (NPTS / CSZ)           // points per CTA = 4096
#define PPT   (PPC / TPB)            // points per thread = 8
#define NWARP (TPB / 32)             // 16

// Selected-index scratch (static device global: allocation-free)
__device__ int g_idx[BATCH * MPTS];

// ---------------- helpers ----------------
__device__ __forceinline__ unsigned smem_u32(const void* p) {
    return (unsigned)__cvta_generic_to_shared(p);
}
__device__ __forceinline__ void cluster_sync_() {
    asm volatile("barrier.cluster.arrive.aligned;" ::: "memory");
    asm volatile("barrier.cluster.wait.aligned;" ::: "memory");
}
__device__ __forceinline__ unsigned mapa_rank(unsigned local_addr, int r) {
    unsigned ret;
    asm("mapa.shared::cluster.u32 %0, %1, %2;" : "=r"(ret) : "r"(local_addr), "r"(r));
    return ret;
}
__device__ __forceinline__ void st_cluster_release_u64(unsigned addr, unsigned long long v) {
    asm volatile("st.release.cluster.shared::cluster.b64 [%0], %1;"
                 :: "r"(addr), "l"(v) : "memory");
}
__device__ __forceinline__ unsigned long long ld_acquire_u64(const unsigned long long* p) {
    unsigned long long v;
    unsigned a = smem_u32(p);
    asm volatile("ld.acquire.cluster.shared::cta.b64 %0, [%1];"
                 : "=l"(v) : "r"(a) : "memory");
    return v;
}
__device__ __forceinline__ unsigned cluster_rank_() {
    unsigned r;
    asm("mov.u32 %0, %%cluster_ctarank;" : "=r"(r));
    return r;
}
__device__ __forceinline__ unsigned redux_max_u32(unsigned v) {
    unsigned r;
    asm volatile("redux.sync.max.u32 %0, %1, 0xffffffff;" : "=r"(r) : "r"(v));
    return r;
}
__device__ __forceinline__ unsigned redux_min_u32(unsigned v) {
    unsigned r;
    asm volatile("redux.sync.min.u32 %0, %1, 0xffffffff;" : "=r"(r) : "r"(v));
    return r;
}

// Reference-exact squared distance (verified bit-exact vs reference; DO NOT TOUCH):
//   inner = fma(dx,dx, rn(dy*dy)); d = fma(dz,dz, inner)
__device__ __forceinline__ float sqdist_ref(float dx, float dy, float dz) {
    float acc = __fmul_rn(dy, dy);
    acc = __fmaf_rn(dx, dx, acc);
    acc = __fmaf_rn(dz, dz, acc);
    return acc;
}

// -------------- FPS kernel ---------------
// Grid: BATCH*CSZ blocks, cluster dims (CSZ,1,1). Each cluster = one batch.
// Per iteration (no cluster.sync in the loop):
//   all threads load centroid coords from global (L2 broadcast),
//   update register-resident min-dists, redux argmax per warp,
//   smem partials + one __syncthreads, warp0 redux over 16 partials,
//   tid0 release-stores packed candidate to all 8 ranks (double-buffered),
//   everyone polls own 8 slots for seq==it, u64-max gives global winner.
__global__ void __launch_bounds__(TPB, 1) __cluster_dims__(CSZ, 1, 1)
fps_kernel(const float* __restrict__ xyz)
{
    const int rank  = (int)cluster_rank_();
    const int batch = blockIdx.x / CSZ;
    const float* __restrict__ xb = xyz + (size_t)batch * 3 * NPTS;
    const int tid  = threadIdx.x;
    const int base = rank * PPC;

    // all-to-all candidate slots, double-buffered by iteration parity
    __shared__ unsigned long long s_slot[2][CSZ];
    // per-warp partials: (distbits<<32)|idx
    __shared__ unsigned long long s_part[NWARP];

    // register-resident point data
    float px[PPT], py[PPT], pz[PPT], dd[PPT];
#pragma unroll
    for (int j = 0; j < PPT; j++) {
        int i = base + j * TPB + tid;
        px[j] = xb[i];
        py[j] = xb[NPTS + i];
        pz[j] = xb[2 * NPTS + i];
        dd[j] = 1e10f;
    }

    if (tid < 2 * CSZ) {
        // seq field init to 0xFFFF (never matches it < 8192)
        s_slot[tid >> 3][tid & (CSZ - 1)] = 0xFFFFull;
    }
    if (rank == 0 && tid == 0) g_idx[batch * MPTS] = 0;  // seed point 0
    cluster_sync_();  // only cluster-wide sync: slots initialized everywhere

    int widx = 0;  // winner of iteration 0

    for (int it = 1; it < MPTS; ++it) {
        // centroid coords: same address across the warp -> single L2-broadcast load
        const float cx = __ldg(xb + widx);
        const float cy = __ldg(xb + NPTS + widx);
        const float cz = __ldg(xb + 2 * NPTS + widx);

        // local update + argmax (dist bits are monotone as uint since dist >= 0)
        unsigned bestd;
        int besti;
        {
            float dx = __fsub_rn(px[0], cx);
            float dy = __fsub_rn(py[0], cy);
            float dz = __fsub_rn(pz[0], cz);
            float nd = fminf(dd[0], sqdist_ref(dx, dy, dz));
            dd[0] = nd;
            bestd = __float_as_uint(nd);
            besti = base + tid;
        }
#pragma unroll
        for (int j = 1; j < PPT; j++) {
            float dx = __fsub_rn(px[j], cx);
            float dy = __fsub_rn(py[j], cy);
            float dz = __fsub_rn(pz[j], cz);
            float nd = fminf(dd[j], sqdist_ref(dx, dy, dz));
            dd[j] = nd;
            unsigned ndb = __float_as_uint(nd);
            if (ndb > bestd) {  // strict > keeps lowest index within thread
                bestd = ndb;
                besti = base + j * TPB + tid;
            }
        }

        // warp argmax via redux: max dist, then min idx among holders
        unsigned wmax = redux_max_u32(bestd);
        unsigned cand = (bestd == wmax) ? (unsigned)besti : 0xFFFFFFFFu;
        unsigned widx_w = redux_min_u32(cand);

        if ((tid & 31) == 0)
            s_part[tid >> 5] = ((unsigned long long)wmax << 32) | widx_w;
        __syncthreads();

        if (tid < 32) {
            // dummy for lanes >= NWARP: dist=0, idx=~0 (loses all comparisons)
            unsigned long long p = (tid < NWARP) ? s_part[tid] : 0xFFFFFFFFull;
            unsigned d32 = (unsigned)(p >> 32);
            unsigned i32 = (unsigned)p;
            unsigned m = redux_max_u32(d32);
            unsigned c = (d32 == m) ? i32 : 0xFFFFFFFFu;
            unsigned gi = redux_min_u32(c);
            if (tid == 0) {
                // packed message: [63:32]=distbits  [30:16]=32767-idx  [15:0]=seq
                unsigned long long msg =
                    ((unsigned long long)m << 32) |
                    ((unsigned long long)(32767u - gi) << 16) |
                    (unsigned long long)(it & 0xFFFF);
                unsigned localSlot = smem_u32(&s_slot[it & 1][rank]);
#pragma unroll
                for (int r = 0; r < CSZ; r++) {
                    st_cluster_release_u64(mapa_rank(localSlot, r), msg);
                }
            }
        }

        // poll own 8 slots until all carry this iteration's seq
        const unsigned seq = (unsigned)(it & 0xFFFF);
        const int buf = it & 1;
        unsigned long long v0, v1, v2, v3, v4, v5, v6, v7;
        bool ok;
        do {
            v0 = ld_acquire_u64(&s_slot[buf][0]);
            v1 = ld_acquire_u64(&s_slot[buf][1]);
            v2 = ld_acquire_u64(&s_slot[buf][2]);
            v3 = ld_acquire_u64(&s_slot[buf][3]);
            v4 = ld_acquire_u64(&s_slot[buf][4]);
            v5 = ld_acquire_u64(&s_slot[buf][5]);
            v6 = ld_acquire_u64(&s_slot[buf][6]);
            v7 = ld_acquire_u64(&s_slot[buf][7]);
            ok = ((unsigned)v0 & 0xFFFFu) == seq && ((unsigned)v1 & 0xFFFFu) == seq &&
                 ((unsigned)v2 & 0xFFFFu) == seq && ((unsigned)v3 & 0xFFFFu) == seq &&
                 ((unsigned)v4 & 0xFFFFu) == seq && ((unsigned)v5 & 0xFFFFu) == seq &&
                 ((unsigned)v6 & 0xFFFFu) == seq && ((unsigned)v7 & 0xFFFFu) == seq;
        } while (!ok);

        // global winner: u64 max = max dist, tie -> larger (32767-idx) = lower idx
        unsigned long long w = v0;
        w = (v1 > w) ? v1 : w;
        w = (v2 > w) ? v2 : w;
        w = (v3 > w) ? v3 : w;
        w = (v4 > w) ? v4 : w;
        w = (v5 > w) ? v5 : w;
        w = (v6 > w) ? v6 : w;
        w = (v7 > w) ? v7 : w;
        widx = 32767 - (int)((w >> 16) & 0x7FFFu);

        if (rank == 0 && tid == 0) g_idx[batch * MPTS + it] = widx;
    }
}

// -------------- gather kernel ---------------
// out = concat( sampled_xyz [B,3,M], sampled_feature [B,Cin,M] )
__global__ void gather_kernel(const float* __restrict__ xyz,
                              const float* __restrict__ feat,
                              float* __restrict__ out)
{
    const long P1  = (long)BATCH * 3 * MPTS;
    const long TOT = P1 + (long)BATCH * CINCH * MPTS;
    long gi = (long)blockIdx.x * blockDim.x + threadIdx.x;
    if (gi >= TOT) return;

    if (gi < P1) {
        int m = (int)(gi % MPTS);
        int c = (int)((gi / MPTS) % 3);
        int b = (int)(gi / ((long)3 * MPTS));
        int idx = g_idx[b * MPTS + m];
        out[gi] = xyz[(size_t)b * 3 * NPTS + (size_t)c * NPTS + idx];
    } else {
        long gj = gi - P1;
        int m = (int)(gj % MPTS);
        int c = (int)((gj / MPTS) % CINCH);
        int b = (int)(gj / ((long)CINCH * MPTS));
        int idx = g_idx[b * MPTS + m];
        out[gi] = feat[(size_t)b * CINCH * NPTS + (size_t)c * NPTS + idx];
    }
}

extern "C" void kernel_launch(void* const* d_in, const int* in_sizes, int n_in,
                              void* d_out, int out_size)
{
    // Defensive: pick xyz by element count (B*3*N = 786432)
    const float* xyz;
    const float* feat;
    if (in_sizes[0] == BATCH * 3 * NPTS) {
        xyz  = (const float*)d_in[0];
        feat = (const float*)d_in[1];
    } else {
        xyz  = (const float*)d_in[1];
        feat = (const float*)d_in[0];
    }
    float* out = (float*)d_out;

    fps_kernel<<<BATCH * CSZ, TPB>>>(xyz);

    const long tot = (long)BATCH * (3 + CINCH) * MPTS;
    const int thr = 256;
    const unsigned blocks = (unsigned)((tot + thr - 1) / thr);
    gather_kernel<<<blocks, thr>>>(xyz, feat, out);
}

// round 5
// speedup vs baseline: 3.2898x; 3.2898x over previous
#include <cuda_runtime.h>
#include <cstdint>

// Problem constants
#define BATCH 8
#define NPTS  32768
#define MPTS  (NPTS / 4)     // 8192
#define CINCH 128

// FPS kernel config: one cluster of CSZ CTAs per batch
#define CSZ   8
#define TPB   512
#define PPC   (NPTS / CSZ)           // points per CTA = 4096
#define PPT   (PPC / TPB)            // points per thread = 8
#define NWARP (TPB / 32)             // 16
#define MSGW  4                      // u64 words per message slot (32B)

// Selected-index scratch (static device global: allocation-free)
__device__ int g_idx[BATCH * MPTS];

// ---------------- helpers ----------------
__device__ __forceinline__ unsigned smem_u32(const void* p) {
    return (unsigned)__cvta_generic_to_shared(p);
}
__device__ __forceinline__ void cluster_sync_() {
    asm volatile("barrier.cluster.arrive.aligned;" ::: "memory");
    asm volatile("barrier.cluster.wait.aligned;" ::: "memory");
}
__device__ __forceinline__ unsigned mapa_rank(unsigned local_addr, int r) {
    unsigned ret;
    asm("mapa.shared::cluster.u32 %0, %1, %2;" : "=r"(ret) : "r"(local_addr), "r"(r));
    return ret;
}
__device__ __forceinline__ void st_cluster_u64(unsigned addr, unsigned long long v) {
    asm volatile("st.shared::cluster.b64 [%0], %1;" :: "r"(addr), "l"(v) : "memory");
}
__device__ __forceinline__ unsigned cluster_rank_() {
    unsigned r;
    asm("mov.u32 %0, %%cluster_ctarank;" : "=r"(r));
    return r;
}
__device__ __forceinline__ unsigned redux_max_u32(unsigned v) {
    unsigned r;
    asm volatile("redux.sync.max.u32 %0, %1, 0xffffffff;" : "=r"(r) : "r"(v));
    return r;
}
__device__ __forceinline__ unsigned redux_min_u32(unsigned v) {
    unsigned r;
    asm volatile("redux.sync.min.u32 %0, %1, 0xffffffff;" : "=r"(r) : "r"(v));
    return r;
}
__device__ __forceinline__ unsigned long long shfl_xor_u64(unsigned long long v, int m) {
    unsigned lo = (unsigned)v, hi = (unsigned)(v >> 32);
    lo = __shfl_xor_sync(0xffffffffu, lo, m);
    hi = __shfl_xor_sync(0xffffffffu, hi, m);
    return ((unsigned long long)hi << 32) | lo;
}

// Reference-exact squared distance (verified bit-exact vs reference; DO NOT TOUCH):
//   inner = fma(dx,dx, rn(dy*dy)); d = fma(dz,dz, inner)
__device__ __forceinline__ float sqdist_ref(float dx, float dy, float dz) {
    float acc = __fmul_rn(dy, dy);
    acc = __fmaf_rn(dx, dx, acc);
    acc = __fmaf_rn(dz, dz, acc);
    return acc;
}

// -------------- FPS kernel ---------------
// Grid: BATCH*CSZ blocks, cluster (CSZ,1,1) = one batch per cluster.
// Per iteration, exactly ONE cluster.sync:
//   update register-resident min-dists vs current centroid (in registers),
//   stage1: per-warp argmax via 2x redux.sync; winner lane writes coords,
//   __syncthreads,
//   stage2 (warp0): u64 butterfly over 16 partials; lanes 0..7 push the CTA
//     candidate (key + coords) to ALL ranks' slots (parity double-buffered),
//   cluster.sync,
//   all threads: max over 8 slots in own smem -> new centroid + index.
__global__ void __launch_bounds__(TPB, 1) __cluster_dims__(CSZ, 1, 1)
fps_kernel(const float* __restrict__ xyz)
{
    const int rank  = (int)cluster_rank_();
    const int batch = blockIdx.x / CSZ;
    const float* __restrict__ xb = xyz + (size_t)batch * 3 * NPTS;
    const int tid  = threadIdx.x;
    const int base = rank * PPC;

    // all-to-all message slots, double-buffered by iteration parity
    // slot r: [r*MSGW+0]=key  [r*MSGW+1]=(y<<32|x)  [r*MSGW+2]=z
    __shared__ unsigned long long s_msg[2][CSZ * MSGW];
    // stage-1 partials
    __shared__ unsigned long long s_key[NWARP];
    __shared__ float s_x[NWARP], s_y[NWARP], s_z[NWARP];

    // register-resident point data
    float px[PPT], py[PPT], pz[PPT], dd[PPT];
#pragma unroll
    for (int j = 0; j < PPT; j++) {
        int i = base + j * TPB + tid;
        px[j] = __ldg(xb + i);
        py[j] = __ldg(xb + NPTS + i);
        pz[j] = __ldg(xb + 2 * NPTS + i);
        dd[j] = 1e10f;
    }

    if (rank == 0 && tid == 0) g_idx[batch * MPTS] = 0;  // seed point 0

    // initial centroid = point 0 (L2 broadcast, once)
    float cx = __ldg(xb);
    float cy = __ldg(xb + NPTS);
    float cz = __ldg(xb + 2 * NPTS);

    cluster_sync_();  // pre-loop alignment (slots unwritten; first write precedes first read)

    const unsigned FULL = 0xffffffffu;

    for (int it = 1; it < MPTS; ++it) {
        // ---- local update + per-thread argmax (uint bits monotone: dist >= 0) ----
        unsigned bestd;
        int besti;
        float bx, by, bz;
        {
            float dx = __fsub_rn(px[0], cx);
            float dy = __fsub_rn(py[0], cy);
            float dz = __fsub_rn(pz[0], cz);
            float nd = fminf(dd[0], sqdist_ref(dx, dy, dz));
            dd[0] = nd;
            bestd = __float_as_uint(nd);
            besti = base + tid;
            bx = px[0]; by = py[0]; bz = pz[0];
        }
#pragma unroll
        for (int j = 1; j < PPT; j++) {
            float dx = __fsub_rn(px[j], cx);
            float dy = __fsub_rn(py[j], cy);
            float dz = __fsub_rn(pz[j], cz);
            float nd = fminf(dd[j], sqdist_ref(dx, dy, dz));
            dd[j] = nd;
            unsigned ndb = __float_as_uint(nd);
            if (ndb > bestd) {  // strict > keeps lowest index within thread
                bestd = ndb;
                besti = base + j * TPB + tid;
                bx = px[j]; by = py[j]; bz = pz[j];
            }
        }

        // ---- stage 1: warp argmax (max dist, ties -> lowest idx) ----
        unsigned wmax  = redux_max_u32(bestd);
        unsigned cand  = (bestd == wmax) ? (unsigned)besti : 0xFFFFFFFFu;
        unsigned wwin  = redux_min_u32(cand);
        const int w = tid >> 5;
        if ((tid & 31) == 0) {
            // key: [63:32]=distbits, [30:16]=32767-idx (u64 max == argmax w/ low-idx tiebreak)
            s_key[w] = ((unsigned long long)wmax << 32) |
                       ((unsigned long long)(32767u - wwin) << 16);
        }
        if ((unsigned)besti == wwin && bestd == wmax) {  // unique winning lane
            s_x[w] = bx; s_y[w] = by; s_z[w] = bz;
        }
        __syncthreads();

        const int buf = it & 1;

        // ---- stage 2 (warp0): reduce 16 partials, push to all ranks ----
        if (tid < 32) {
            unsigned long long key = (tid < NWARP) ? s_key[tid] : 0ull;
            int wsrc = (tid < NWARP) ? tid : 0;
#pragma unroll
            for (int off = 16; off > 0; off >>= 1) {
                unsigned long long ok = shfl_xor_u64(key, off);
                int ow = __shfl_xor_sync(FULL, wsrc, off);
                if (ok > key) { key = ok; wsrc = ow; }
            }
            // every lane now holds the CTA-winning (key, source warp)
            if (tid < CSZ) {
                float wx = s_x[wsrc], wy = s_y[wsrc], wz = s_z[wsrc];
                unsigned long long xy =
                    ((unsigned long long)__float_as_uint(wy) << 32) | __float_as_uint(wx);
                unsigned long long zz = (unsigned long long)__float_as_uint(wz);
                unsigned localSlot = smem_u32(&s_msg[buf][rank * MSGW]);
                unsigned ra = mapa_rank(localSlot, tid);  // lane t -> rank t
                st_cluster_u64(ra,      key);
                st_cluster_u64(ra + 8,  xy);
                st_cluster_u64(ra + 16, zz);
            }
        }

        cluster_sync_();  // the only per-iteration cluster barrier

        // ---- extract global winner from own smem (all threads) ----
        unsigned long long bk = s_msg[buf][0];
        int br = 0;
#pragma unroll
        for (int r = 1; r < CSZ; r++) {
            unsigned long long k = s_msg[buf][r * MSGW];
            if (k > bk) { bk = k; br = r; }
        }
        unsigned long long xy = s_msg[buf][br * MSGW + 1];
        unsigned long long zz = s_msg[buf][br * MSGW + 2];
        cx = __uint_as_float((unsigned)xy);
        cy = __uint_as_float((unsigned)(xy >> 32));
        cz = __uint_as_float((unsigned)zz);
        int widx = 32767 - (int)((bk >> 16) & 0x7FFFu);

        if (rank == 0 && tid == 0) g_idx[batch * MPTS + it] = widx;
    }
}

// -------------- gather kernel ---------------
// out = concat( sampled_xyz [B,3,M], sampled_feature [B,Cin,M] )
__global__ void gather_kernel(const float* __restrict__ xyz,
                              const float* __restrict__ feat,
                              float* __restrict__ out)
{
    const long P1  = (long)BATCH * 3 * MPTS;
    const long TOT = P1 + (long)BATCH * CINCH * MPTS;
    long gi = (long)blockIdx.x * blockDim.x + threadIdx.x;
    if (gi >= TOT) return;

    if (gi < P1) {
        int m = (int)(gi % MPTS);
        int c = (int)((gi / MPTS) % 3);
        int b = (int)(gi / ((long)3 * MPTS));
        int idx = g_idx[b * MPTS + m];
        out[gi] = xyz[(size_t)b * 3 * NPTS + (size_t)c * NPTS + idx];
    } else {
        long gj = gi - P1;
        int m = (int)(gj % MPTS);
        int c = (int)((gj / MPTS) % CINCH);
        int b = (int)(gj / ((long)CINCH * MPTS));
        int idx = g_idx[b * MPTS + m];
        out[gi] = feat[(size_t)b * CINCH * NPTS + (size_t)c * NPTS + idx];
    }
}

extern "C" void kernel_launch(void* const* d_in, const int* in_sizes, int n_in,
                              void* d_out, int out_size)
{
    // Defensive: pick xyz by element count (B*3*N = 786432)
    const float* xyz;
    const float* feat;
    if (in_sizes[0] == BATCH * 3 * NPTS) {
        xyz  = (const float*)d_in[0];
        feat = (const float*)d_in[1];
    } else {
        xyz  = (const float*)d_in[1];
        feat = (const float*)d_in[0];
    }
    float* out = (float*)d_out;

    fps_kernel<<<BATCH * CSZ, TPB>>>(xyz);

    const long tot = (long)BATCH * (3 + CINCH) * MPTS;
    const int thr = 256;
    const unsigned blocks = (unsigned)((tot + thr - 1) / thr);
    gather_kernel<<<blocks, thr>>>(xyz, feat, out);
}

// round 6
// speedup vs baseline: 3.5376x; 1.0753x over previous
#include <cuda_runtime.h>
#include <cstdint>

// Problem constants
#define BATCH 8
#define NPTS  32768
#define MPTS  (NPTS / 4)     // 8192
#define CINCH 128

// FPS kernel config: one cluster of CSZ CTAs per batch
#define CSZ   8
#define TPB   512
#define PPC   (NPTS / CSZ)           // points per CTA = 4096
#define PPT   (PPC / TPB)            // points per thread = 8
#define NPAIR (PPT / 2)              // f32x2 pairs per thread = 4
#define NWARP (TPB / 32)             // 16
#define MSGW  4                      // u64 words per message slot (32B)

// Selected-index scratch (static device global: allocation-free)
__device__ int g_idx[BATCH * MPTS];

// ---------------- helpers ----------------
__device__ __forceinline__ unsigned smem_u32(const void* p) {
    return (unsigned)__cvta_generic_to_shared(p);
}
__device__ __forceinline__ void cluster_sync_() {
    asm volatile("barrier.cluster.arrive.aligned;" ::: "memory");
    asm volatile("barrier.cluster.wait.aligned;" ::: "memory");
}
__device__ __forceinline__ unsigned mapa_rank(unsigned local_addr, int r) {
    unsigned ret;
    asm("mapa.shared::cluster.u32 %0, %1, %2;" : "=r"(ret) : "r"(local_addr), "r"(r));
    return ret;
}
__device__ __forceinline__ void st_cluster_u64(unsigned addr, unsigned long long v) {
    asm volatile("st.shared::cluster.b64 [%0], %1;" :: "r"(addr), "l"(v) : "memory");
}
__device__ __forceinline__ unsigned cluster_rank_() {
    unsigned r;
    asm("mov.u32 %0, %%cluster_ctarank;" : "=r"(r));
    return r;
}
__device__ __forceinline__ unsigned redux_max_u32(unsigned v) {
    unsigned r;
    asm volatile("redux.sync.max.u32 %0, %1, 0xffffffff;" : "=r"(r) : "r"(v));
    return r;
}
__device__ __forceinline__ unsigned redux_min_u32(unsigned v) {
    unsigned r;
    asm volatile("redux.sync.min.u32 %0, %1, 0xffffffff;" : "=r"(r) : "r"(v));
    return r;
}
__device__ __forceinline__ unsigned long long shfl_xor_u64(unsigned long long v, int m) {
    unsigned lo = (unsigned)v, hi = (unsigned)(v >> 32);
    lo = __shfl_xor_sync(0xffffffffu, lo, m);
    hi = __shfl_xor_sync(0xffffffffu, hi, m);
    return ((unsigned long long)hi << 32) | lo;
}

// mbarrier ops
__device__ __forceinline__ void mbar_init(unsigned addr, unsigned count) {
    asm volatile("mbarrier.init.shared.b64 [%0], %1;" :: "r"(addr), "r"(count) : "memory");
}
__device__ __forceinline__ void mbar_arrive_remote(unsigned remote_addr) {
    asm volatile("mbarrier.arrive.release.cluster.shared::cluster.b64 _, [%0];"
                 :: "r"(remote_addr) : "memory");
}
__device__ __forceinline__ void mbar_wait(unsigned addr, unsigned parity) {
    asm volatile(
        "{\n\t"
        ".reg .pred P;\n\t"
        "WAIT_%=: \n\t"
        "mbarrier.try_wait.parity.acquire.cluster.shared::cta.b64 P, [%0], %1, 0x989680;\n\t"
        "@P bra.uni DONE_%=;\n\t"
        "bra.uni WAIT_%=;\n\t"
        "DONE_%=: \n\t"
        "}"
        :: "r"(addr), "r"(parity) : "memory");
}

// packed f32x2 ops (per-lane rn semantics == scalar rn; bit-exact)
#define ADD2(out, a, b) asm("add.rn.f32x2 %0, %1, %2;" : "=l"(out) : "l"(a), "l"(b))
#define MUL2(out, a, b) asm("mul.rn.f32x2 %0, %1, %2;" : "=l"(out) : "l"(a), "l"(b))
#define FMA2(out, a, b, c) asm("fma.rn.f32x2 %0, %1, %2, %3;" : "=l"(out) : "l"(a), "l"(b), "l"(c))
#define PACK2(out, lo, hi) asm("mov.b64 %0, {%1, %2};" : "=l"(out) : "f"(lo), "f"(hi))
#define UNPACK2(lo, hi, in) asm("mov.b64 {%0, %1}, %2;" : "=f"(lo), "=f"(hi) : "l"(in))

// Reference-exact squared distance (verified bit-exact; DO NOT TOUCH):
//   d = fma(dz,dz, fma(dx,dx, rn(dy*dy)))   and  dx computed as rn(px + (-cx))

// -------------- FPS kernel ---------------
// Grid: BATCH*CSZ blocks, cluster (CSZ,1,1) = one batch per cluster.
// Per iteration, NO cluster.sync: mbarrier (count=8) per CTA; lanes 0..7 of
// warp0 push the CTA candidate (key+coords) to every rank's slot and do a
// release-arrive on that rank's mbarrier; all threads acquire-try_wait.
__global__ void __launch_bounds__(TPB, 1) __cluster_dims__(CSZ, 1, 1)
fps_kernel(const float* __restrict__ xyz)
{
    const int rank  = (int)cluster_rank_();
    const int batch = blockIdx.x / CSZ;
    const float* __restrict__ xb = xyz + (size_t)batch * 3 * NPTS;
    const int tid  = threadIdx.x;
    const int base = rank * PPC;

    // all-to-all message slots, double-buffered by iteration parity
    // slot r: [0]=key  [1]=(y<<32|x)  [2]=z
    __shared__ unsigned long long s_msg[2][CSZ * MSGW];
    __shared__ unsigned long long s_key[NWARP];
    __shared__ unsigned long long s_mbar;
    // coord mirror (read-only after init; used for winner coord extraction)
    __shared__ float s_px[PPC], s_py[PPC], s_pz[PPC];

    // register-resident packed point data + scalar min-dists
    unsigned long long px2[NPAIR], py2[NPAIR], pz2[NPAIR];
    float dd[PPT];
#pragma unroll
    for (int jp = 0; jp < NPAIR; jp++) {
        int l0 = (2 * jp) * TPB + tid;
        int l1 = l0 + TPB;
        float x0 = __ldg(xb + base + l0), x1 = __ldg(xb + base + l1);
        float y0 = __ldg(xb + NPTS + base + l0), y1 = __ldg(xb + NPTS + base + l1);
        float z0 = __ldg(xb + 2 * NPTS + base + l0), z1 = __ldg(xb + 2 * NPTS + base + l1);
        PACK2(px2[jp], x0, x1);
        PACK2(py2[jp], y0, y1);
        PACK2(pz2[jp], z0, z1);
        s_px[l0] = x0; s_px[l1] = x1;
        s_py[l0] = y0; s_py[l1] = y1;
        s_pz[l0] = z0; s_pz[l1] = z1;
        dd[2 * jp] = 1e10f;
        dd[2 * jp + 1] = 1e10f;
    }

    if (tid == 0) mbar_init(smem_u32(&s_mbar), CSZ);
    if (rank == 0 && tid == 0) g_idx[batch * MPTS] = 0;  // seed point 0

    // initial centroid = point 0
    float cx = __ldg(xb);
    float cy = __ldg(xb + NPTS);
    float cz = __ldg(xb + 2 * NPTS);

    __syncthreads();
    cluster_sync_();  // once: mbarriers + mirrors initialized cluster-wide

    const unsigned mbarAddr = smem_u32(&s_mbar);

    for (int it = 1; it < MPTS; ++it) {
        // packed negated centroid (rn(a + (-b)) == rn(a - b), bit-exact)
        unsigned long long ncx2, ncy2, ncz2;
        {
            float nx = -cx, ny = -cy, nz = -cz;
            PACK2(ncx2, nx, nx);
            PACK2(ncy2, ny, ny);
            PACK2(ncz2, nz, nz);
        }

        // ---- local update + per-thread argmax (uint bits monotone: dist >= 0) ----
        unsigned bestd = 0;
        int bj = 0;
#pragma unroll
        for (int jp = 0; jp < NPAIR; jp++) {
            unsigned long long dx2, dy2, dz2, t2;
            ADD2(dx2, px2[jp], ncx2);
            ADD2(dy2, py2[jp], ncy2);
            ADD2(dz2, pz2[jp], ncz2);
            MUL2(t2, dy2, dy2);               // rn(dy*dy)
            FMA2(t2, dx2, dx2, t2);           // fma(dx,dx, .)
            FMA2(t2, dz2, dz2, t2);           // fma(dz,dz, .)
            float d0, d1;
            UNPACK2(d0, d1, t2);
            float n0 = fminf(dd[2 * jp], d0);
            float n1 = fminf(dd[2 * jp + 1], d1);
            dd[2 * jp] = n0;
            dd[2 * jp + 1] = n1;
            unsigned nb0 = __float_as_uint(n0);
            if (nb0 > bestd) { bestd = nb0; bj = 2 * jp; }      // strict >: lowest j wins
            unsigned nb1 = __float_as_uint(n1);
            if (nb1 > bestd) { bestd = nb1; bj = 2 * jp + 1; }
        }
        int besti = base + bj * TPB + tid;

        // ---- stage 1: warp argmax (max dist, ties -> lowest idx) ----
        unsigned wmax = redux_max_u32(bestd);
        unsigned cand = (bestd == wmax) ? (unsigned)besti : 0xFFFFFFFFu;
        unsigned wwin = redux_min_u32(cand);
        if ((tid & 31) == 0) {
            // key: [63:32]=distbits, [30:16]=32767-idx (u64 max == argmax, low-idx tiebreak)
            s_key[tid >> 5] = ((unsigned long long)wmax << 32) |
                              ((unsigned long long)(32767u - wwin) << 16);
        }
        __syncthreads();

        const int buf = it & 1;

        // ---- stage 2 (warp0): butterfly over 16 partials; push to all ranks ----
        if (tid < 32) {
            unsigned long long key = (tid < NWARP) ? s_key[tid] : 0ull;
#pragma unroll
            for (int off = 8; off > 0; off >>= 1) {
                unsigned long long ok = shfl_xor_u64(key, off);
                if (ok > key) key = ok;
            }
            if (tid < CSZ) {
                int wi = 32767 - (int)((key >> 16) & 0x7FFFu);  // CTA-local winner idx
                int li = wi - base;
                float wx = s_px[li], wy = s_py[li], wz = s_pz[li];
                unsigned long long xy, zz;
                PACK2(xy, wx, wy);
                zz = (unsigned long long)__float_as_uint(wz);
                unsigned localSlot = smem_u32(&s_msg[buf][rank * MSGW]);
                unsigned ra = mapa_rank(localSlot, tid);   // lane t -> rank t
                st_cluster_u64(ra,      key);
                st_cluster_u64(ra + 8,  xy);
                st_cluster_u64(ra + 16, zz);
                mbar_arrive_remote(mapa_rank(mbarAddr, tid));
            }
        }

        // ---- wait for all 8 CTA candidates (phase parity) ----
        mbar_wait(mbarAddr, (unsigned)((it - 1) & 1));

        // ---- extract global winner from own smem ----
        unsigned long long bk = s_msg[buf][0];
        int br = 0;
#pragma unroll
        for (int r = 1; r < CSZ; r++) {
            unsigned long long k = s_msg[buf][r * MSGW];
            if (k > bk) { bk = k; br = r; }
        }
        unsigned long long xy = s_msg[buf][br * MSGW + 1];
        unsigned long long zz = s_msg[buf][br * MSGW + 2];
        UNPACK2(cx, cy, xy);
        cz = __uint_as_float((unsigned)zz);
        int widx = 32767 - (int)((bk >> 16) & 0x7FFFu);

        if (rank == 0 && tid == 0) g_idx[batch * MPTS + it] = widx;
    }
}

// -------------- gather kernel ---------------
// out = concat( sampled_xyz [B,3,M], sampled_feature [B,Cin,M] )
__global__ void gather_kernel(const float* __restrict__ xyz,
                              const float* __restrict__ feat,
                              float* __restrict__ out)
{
    const long P1  = (long)BATCH * 3 * MPTS;
    const long TOT = P1 + (long)BATCH * CINCH * MPTS;
    long gi = (long)blockIdx.x * blockDim.x + threadIdx.x;
    if (gi >= TOT) return;

    if (gi < P1) {
        int m = (int)(gi % MPTS);
        int c = (int)((gi / MPTS) % 3);
        int b = (int)(gi / ((long)3 * MPTS));
        int idx = g_idx[b * MPTS + m];
        out[gi] = xyz[(size_t)b * 3 * NPTS + (size_t)c * NPTS + idx];
    } else {
        long gj = gi - P1;
        int m = (int)(gj % MPTS);
        int c = (int)((gj / MPTS) % CINCH);
        int b = (int)(gj / ((long)CINCH * MPTS));
        int idx = g_idx[b * MPTS + m];
        out[gi] = feat[(size_t)b * CINCH * NPTS + (size_t)c * NPTS + idx];
    }
}

extern "C" void kernel_launch(void* const* d_in, const int* in_sizes, int n_in,
                              void* d_out, int out_size)
{
    // Defensive: pick xyz by element count (B*3*N = 786432)
    const float* xyz;
    const float* feat;
    if (in_sizes[0] == BATCH * 3 * NPTS) {
        xyz  = (const float*)d_in[0];
        feat = (const float*)d_in[1];
    } else {
        xyz  = (const float*)d_in[1];
        feat = (const float*)d_in[0];
    }
    float* out = (float*)d_out;

    fps_kernel<<<BATCH * CSZ, TPB>>>(xyz);

    const long tot = (long)BATCH * (3 + CINCH) * MPTS;
    const int thr = 256;
    const unsigned blocks = (unsigned)((tot + thr - 1) / thr);
    gather_kernel<<<blocks, thr>>>(xyz, feat, out);
}